// round 16
// baseline (speedup 1.0000x reference)
#include <cuda_runtime.h>
#include <math.h>

#define K_BINS   8
#define TAIL     3.0f
#define MIN_W    0.001f
#define MIN_H    0.001f
#define MIN_D    0.001f

#define NROWS    8192
#define NDIMS    2048
#define NPAR     (K_BINS * 3 - 1)   // 23

#define TILE_D   64                  // columns per block
#define THREADS  128                 // 32 col-pairs x 4 row slots
#define ROWS_PB  64                  // rows per block (4 slots x 16 rows)

// per-column-block table image (floats), per bin b (stride 384 floats = 1536 B):
//   [b*384 + par*128 + 4t , +4): float4 {invw, c, ih, ich}   col = 2t+par
//   [b*384 + 256 + par*64 + 2t, +2): float2 {dlo, s}
// knots at [3072, 3520): kn[7][64]
#define TBL_BIN  384
#define TBL_KN   3072
#define TBL_SZ   3520
#define NBLK_D   (NDIMS / TILE_D)    // 32

__device__ __align__(16) float g_tbl[NBLK_D * TBL_SZ];   // 450 KB device scratch
__device__ int g_flag[NBLK_D];                           // zero-init; sticky across replays

// one spline-element evaluation; par must be compile-time (0 or 1)
// x is pre-clamped to [-TAIL, TAIL]; logdet needs no outside-select
// (edge derivatives are exactly 1.0 -> logdet(boundary) = log(1) = 0).
__device__ __forceinline__ void rqs_one(
    const float g,
    const float k0, const float k1, const float k2, const float k3,
    const float k4, const float k5, const float k6,
    const float* __restrict__ qA,   // sm + 4*tx   (float4 record base)
    const float* __restrict__ qB,   // sm + 256 + 2*tx (float2 record base)
    const int par,
    float& r_o, float& r_l)
{
    const float x = fminf(fmaxf(g, -TAIL), TAIL);

    const bool p3 = x >= k3;
    const float m1 = p3 ? k5 : k1;
    const bool p2 = x >= m1;
    const float hi = p2 ? k6 : k4;
    const float lo = p2 ? k2 : k0;
    const float m2 = p3 ? hi : lo;
    const bool p1 = x >= m2;
    const int idx = (p3 ? 4 : 0) + (p2 ? 2 : 0) + (p1 ? 1 : 0);
    const int off = idx * TBL_BIN;               // shared by both loads

    const float4 A = *(const float4*)(qA + off + par * 128);   // {invw, c, ih, ich}
    const float2 B = *(const float2*)(qB + off + par * 64);    // {dlo, s}

    const float delta = A.z * A.x;           // ih * invw
    const float th  = fmaf(x, A.x, A.y);     // theta
    const float th2 = th * th;
    const float t1m = th - th2;              // theta*(1-theta)

    const float den  = fmaf(B.y, t1m, delta);
    const float rden = __fdividef(1.0f, den);

    const float nm = fmaf(delta, th2, B.x * t1m);
    const float o  = fmaf(A.z * nm, rden, A.w);

    const float dmd = delta - B.x;
    const float dn  = fmaf(fmaf(B.y, th, dmd + dmd), th, B.x);
    const float dd  = delta * rden;
    r_l = __logf(dn * (dd * dd));

    r_o = (x == g) ? o : g;                  // identity outside the tail
}

__global__ __launch_bounds__(THREADS, 8)
void rqs_fused(const float* __restrict__ inputs,
               const float* __restrict__ params,
               float* __restrict__ out_base)
{
    __shared__ __align__(16) float sm[TBL_SZ];    // 13.75 KB table image

    const int tid = threadIdx.x;
    const int bx  = blockIdx.x;

    if (blockIdx.y == 0) {
        // ---------------- builder path (first 32 scheduled blocks) ----------------
        {
            const float* gsrc = params + (size_t)bx * TILE_D * NPAR;
            #pragma unroll
            for (int i = 0; i < (TILE_D * NPAR + THREADS - 1) / THREADS; i++) {
                const int k = tid + i * THREADS;
                if (k < TILE_D * NPAR) sm[k] = gsrc[k];
            }
        }
        __syncthreads();

        float uw[K_BINS], uh[K_BINS], ud[K_BINS - 1];
        if (tid < TILE_D) {
            const float* sp = sm + tid * NPAR;   // stride 23: conflict-free
            #pragma unroll
            for (int j = 0; j < K_BINS; j++)      uw[j] = sp[j];
            #pragma unroll
            for (int j = 0; j < K_BINS; j++)      uh[j] = sp[K_BINS + j];
            #pragma unroll
            for (int j = 0; j < K_BINS - 1; j++)  ud[j] = sp[2 * K_BINS + j];
        }
        __syncthreads();   // scratch reads done before tables overwrite

        if (tid < TILE_D) {
            float cw[K_BINS + 1], ch[K_BINS + 1];
            {
                float m = uw[0];
                #pragma unroll
                for (int j = 1; j < K_BINS; j++) m = fmaxf(m, uw[j]);
                float e[K_BINS], ssum = 0.0f;
                #pragma unroll
                for (int j = 0; j < K_BINS; j++) { e[j] = expf(uw[j] - m); ssum += e[j]; }
                float inv_s = 1.0f / ssum;
                float acc = 0.0f;
                cw[0] = -TAIL;
                #pragma unroll
                for (int j = 0; j < K_BINS; j++) {
                    float wj = fmaf(1.0f - MIN_W * K_BINS, e[j] * inv_s, MIN_W);
                    acc += wj;
                    cw[j + 1] = fmaf(2.0f * TAIL, acc, -TAIL);
                }
                cw[K_BINS] = TAIL;
            }
            {
                float m = uh[0];
                #pragma unroll
                for (int j = 1; j < K_BINS; j++) m = fmaxf(m, uh[j]);
                float e[K_BINS], ssum = 0.0f;
                #pragma unroll
                for (int j = 0; j < K_BINS; j++) { e[j] = expf(uh[j] - m); ssum += e[j]; }
                float inv_s = 1.0f / ssum;
                float acc = 0.0f;
                ch[0] = -TAIL;
                #pragma unroll
                for (int j = 0; j < K_BINS; j++) {
                    float hj = fmaf(1.0f - MIN_H * K_BINS, e[j] * inv_s, MIN_H);
                    acc += hj;
                    ch[j + 1] = fmaf(2.0f * TAIL, acc, -TAIL);
                }
                ch[K_BINS] = TAIL;
            }
            float dv[K_BINS + 1];
            dv[0] = 1.0f;              // MIN_D + softplus(log(exp(1-MIN_D)-1)) == 1
            dv[K_BINS] = 1.0f;
            #pragma unroll
            for (int j = 0; j < K_BINS - 1; j++)
                dv[j + 1] = MIN_D + log1pf(expf(ud[j]));

            const int tx  = tid >> 1;
            const int par = tid & 1;

            #pragma unroll
            for (int j = 0; j < 7; j++) sm[TBL_KN + j * TILE_D + tid] = cw[j + 1];

            #pragma unroll
            for (int b = 0; b < K_BINS; b++) {
                const float iw    = cw[b + 1] - cw[b];
                const float ih    = ch[b + 1] - ch[b];
                const float invw  = 1.0f / iw;
                const float delta = ih * invw;
                const float dlo   = dv[b];
                const float s     = dlo + dv[b + 1] - 2.0f * delta;
                const int o4 = b * TBL_BIN + par * 128 + tx * 4;
                sm[o4 + 0] = invw;
                sm[o4 + 1] = -cw[b] * invw;
                sm[o4 + 2] = ih;
                sm[o4 + 3] = ch[b];
                const int o2 = b * TBL_BIN + 256 + par * 64 + tx * 2;
                sm[o2 + 0] = dlo;
                sm[o2 + 1] = s;
            }
        }
        __syncthreads();

        // mirror to global and publish
        {
            float4* dst = (float4*)(g_tbl + (size_t)bx * TBL_SZ);
            const float4* src = (const float4*)sm;
            #pragma unroll
            for (int i = 0; i < 7; i++) {
                const int k = tid + i * THREADS;
                if (k < TBL_SZ / 4) dst[k] = src[k];
            }
        }
        __threadfence();
        __syncthreads();
        if (tid == 0) atomicExch(&g_flag[bx], 1);
    } else {
        // ---------------- consumer path ----------------
        if (tid == 0) {
            while (atomicAdd(&g_flag[bx], 0) == 0) __nanosleep(64);
        }
        __syncthreads();
        const float4* src = (const float4*)(g_tbl + (size_t)bx * TBL_SZ);
        float4* dst = (float4*)sm;
        #pragma unroll
        for (int i = 0; i < 7; i++) {
            const int k = tid + i * THREADS;
            if (k < TBL_SZ / 4) dst[k] = __ldcg(src + k);   // L1-bypass: L2-fresh
        }
        __syncthreads();
    }

    // ---------------- main elementwise loop ----------------
    const int tx  = tid & 31;                    // col-pair index
    const int ty  = tid >> 5;                    // row slot 0..3
    const int col = bx * TILE_D + 2 * tx;
    const int row0 = blockIdx.y * ROWS_PB + ty;

    const float* kn = sm + TBL_KN;
    const float ka0 = kn[0*64 + 2*tx],   ka1 = kn[1*64 + 2*tx],   ka2 = kn[2*64 + 2*tx];
    const float ka3 = kn[3*64 + 2*tx],   ka4 = kn[4*64 + 2*tx],   ka5 = kn[5*64 + 2*tx];
    const float ka6 = kn[6*64 + 2*tx];
    const float kb0 = kn[0*64 + 2*tx+1], kb1 = kn[1*64 + 2*tx+1], kb2 = kn[2*64 + 2*tx+1];
    const float kb3 = kn[3*64 + 2*tx+1], kb4 = kn[4*64 + 2*tx+1], kb5 = kn[5*64 + 2*tx+1];
    const float kb6 = kn[6*64 + 2*tx+1];

    const float* qA = sm + 4 * tx;          // float4 record lane base
    const float* qB = sm + 256 + 2 * tx;    // float2 record lane base

    const size_t base = (size_t)row0 * NDIMS + col;
    const float2* __restrict__ pin = (const float2*)(inputs + base);
    float2* __restrict__ po = (float2*)(out_base + base);
    float2* __restrict__ pl = (float2*)(out_base + (size_t)NROWS * NDIMS + base);
    const int RSTRIDE = 4 * NDIMS / 2;           // float2 units per 4-row step

    #pragma unroll 1
    for (int ii = 0; ii < 2; ii++) {
        float2 gv[8];
        #pragma unroll
        for (int j = 0; j < 8; j++) gv[j] = pin[j * RSTRIDE];

        #pragma unroll
        for (int j = 0; j < 8; j++) {
            float2 ro, rl;
            rqs_one(gv[j].x, ka0, ka1, ka2, ka3, ka4, ka5, ka6, qA, qB, 0, ro.x, rl.x);
            rqs_one(gv[j].y, kb0, kb1, kb2, kb3, kb4, kb5, kb6, qA, qB, 1, ro.y, rl.y);
            po[j * RSTRIDE] = ro;
            pl[j * RSTRIDE] = rl;
        }
        pin += 8 * RSTRIDE;
        po  += 8 * RSTRIDE;
        pl  += 8 * RSTRIDE;
    }
}

extern "C" void kernel_launch(void* const* d_in, const int* in_sizes, int n_in,
                              void* d_out, int out_size)
{
    const float* inputs = (const float*)d_in[0];
    const float* params = (const float*)d_in[1];
    float* out = (float*)d_out;

    dim3 grid(NBLK_D, NROWS / ROWS_PB);   // (32, 128)
    rqs_fused<<<grid, THREADS>>>(inputs, params, out);
}

// round 17
// speedup vs baseline: 1.0607x; 1.0607x over previous
#include <cuda_runtime.h>
#include <math.h>

#define K_BINS   8
#define TAIL     3.0f
#define MIN_W    0.001f
#define MIN_H    0.001f
#define MIN_D    0.001f

#define NROWS    8192
#define NDIMS    2048
#define NPAR     (K_BINS * 3 - 1)   // 23

#define TILE_D   64                  // columns per block
#define THREADS  128                 // 32 col-pairs x 4 row slots
#define TILE_R   16                  // rows per tile (4 slots x 4 rows)
#define NTILES   (NROWS / TILE_R)    // 512
#define GRID_Y   41                  // 32*41 = 1312 <= 148*9 resident CTAs

// per-column-block table image (floats), per bin b (stride 384 floats = 1536 B):
//   [b*384 + par*128 + 4t , +4): float4 {invw, c, ih, ich}   col = 2t+par
//   [b*384 + 256 + par*64 + 2t, +2): float2 {dlo, s}
// knots at [3072, 3520): kn[7][64]
#define TBL_BIN  384
#define TBL_KN   3072
#define TBL_SZ   3520
#define NBLK_D   (NDIMS / TILE_D)    // 32

__device__ __align__(16) float g_tbl[NBLK_D * TBL_SZ];   // 450 KB device scratch
__device__ int g_flag[NBLK_D];                           // zero-init; sticky across replays

// one spline-element evaluation; par must be compile-time (0 or 1)
__device__ __forceinline__ void rqs_one(
    const float g,
    const float k0, const float k1, const float k2, const float k3,
    const float k4, const float k5, const float k6,
    const float* __restrict__ qA,   // sm + 4*tx   (float4 record base)
    const float* __restrict__ qB,   // sm + 256 + 2*tx (float2 record base)
    const int par,
    float& r_o, float& r_l)
{
    const bool p3 = g >= k3;
    const float m1 = p3 ? k5 : k1;
    const bool p2 = g >= m1;
    const float hi = p2 ? k6 : k4;
    const float lo = p2 ? k2 : k0;
    const float m2 = p3 ? hi : lo;
    const bool p1 = g >= m2;
    const int idx = (p3 ? 4 : 0) + (p2 ? 2 : 0) + (p1 ? 1 : 0);
    const int off = idx * TBL_BIN;               // shared by both loads

    const float4 A = *(const float4*)(qA + off + par * 128);   // {invw, c, ih, ich}
    const float2 B = *(const float2*)(qB + off + par * 64);    // {dlo, s}

    const float delta = A.z * A.x;           // ih * invw
    const float th  = fmaf(g, A.x, A.y);     // theta
    const float th2 = th * th;
    const float t1m = th - th2;              // theta*(1-theta)

    const float den  = fmaf(B.y, t1m, delta);
    const float rden = __fdividef(1.0f, den);

    const float nm = fmaf(delta, th2, B.x * t1m);
    const float o  = fmaf(A.z * nm, rden, A.w);

    const float dmd = delta - B.x;
    const float dn  = fmaf(fmaf(B.y, th, dmd + dmd), th, B.x);
    const float dd  = delta * rden;
    const float l   = __logf(dn * (dd * dd));

    const bool inside = fabsf(g) <= TAIL;
    r_o = inside ? o : g;
    r_l = inside ? l : 0.0f;
}

__global__ __launch_bounds__(THREADS, 9)
void rqs_fused(const float* __restrict__ inputs,
               const float* __restrict__ params,
               float* __restrict__ out_base)
{
    __shared__ __align__(16) float sm[TBL_SZ];    // 13.75 KB table image

    const int tid = threadIdx.x;
    const int bx  = blockIdx.x;

    if (blockIdx.y == 0) {
        // ---------------- builder path (32 blocks, all wave-1 resident) ----------------
        {
            const float* gsrc = params + (size_t)bx * TILE_D * NPAR;
            #pragma unroll
            for (int i = 0; i < (TILE_D * NPAR + THREADS - 1) / THREADS; i++) {
                const int k = tid + i * THREADS;
                if (k < TILE_D * NPAR) sm[k] = gsrc[k];
            }
        }
        __syncthreads();

        float uw[K_BINS], uh[K_BINS], ud[K_BINS - 1];
        if (tid < TILE_D) {
            const float* sp = sm + tid * NPAR;   // stride 23: conflict-free
            #pragma unroll
            for (int j = 0; j < K_BINS; j++)      uw[j] = sp[j];
            #pragma unroll
            for (int j = 0; j < K_BINS; j++)      uh[j] = sp[K_BINS + j];
            #pragma unroll
            for (int j = 0; j < K_BINS - 1; j++)  ud[j] = sp[2 * K_BINS + j];
        }
        __syncthreads();   // scratch reads done before tables overwrite

        if (tid < TILE_D) {
            float cw[K_BINS + 1], ch[K_BINS + 1];
            {
                float m = uw[0];
                #pragma unroll
                for (int j = 1; j < K_BINS; j++) m = fmaxf(m, uw[j]);
                float e[K_BINS], ssum = 0.0f;
                #pragma unroll
                for (int j = 0; j < K_BINS; j++) { e[j] = expf(uw[j] - m); ssum += e[j]; }
                float inv_s = 1.0f / ssum;
                float acc = 0.0f;
                cw[0] = -TAIL;
                #pragma unroll
                for (int j = 0; j < K_BINS; j++) {
                    float wj = fmaf(1.0f - MIN_W * K_BINS, e[j] * inv_s, MIN_W);
                    acc += wj;
                    cw[j + 1] = fmaf(2.0f * TAIL, acc, -TAIL);
                }
                cw[K_BINS] = TAIL;
            }
            {
                float m = uh[0];
                #pragma unroll
                for (int j = 1; j < K_BINS; j++) m = fmaxf(m, uh[j]);
                float e[K_BINS], ssum = 0.0f;
                #pragma unroll
                for (int j = 0; j < K_BINS; j++) { e[j] = expf(uh[j] - m); ssum += e[j]; }
                float inv_s = 1.0f / ssum;
                float acc = 0.0f;
                ch[0] = -TAIL;
                #pragma unroll
                for (int j = 0; j < K_BINS; j++) {
                    float hj = fmaf(1.0f - MIN_H * K_BINS, e[j] * inv_s, MIN_H);
                    acc += hj;
                    ch[j + 1] = fmaf(2.0f * TAIL, acc, -TAIL);
                }
                ch[K_BINS] = TAIL;
            }
            float dv[K_BINS + 1];
            dv[0] = 1.0f;              // MIN_D + softplus(log(exp(1-MIN_D)-1)) == 1
            dv[K_BINS] = 1.0f;
            #pragma unroll
            for (int j = 0; j < K_BINS - 1; j++)
                dv[j + 1] = MIN_D + log1pf(expf(ud[j]));

            const int tx  = tid >> 1;
            const int par = tid & 1;

            #pragma unroll
            for (int j = 0; j < 7; j++) sm[TBL_KN + j * TILE_D + tid] = cw[j + 1];

            #pragma unroll
            for (int b = 0; b < K_BINS; b++) {
                const float iw    = cw[b + 1] - cw[b];
                const float ih    = ch[b + 1] - ch[b];
                const float invw  = 1.0f / iw;
                const float delta = ih * invw;
                const float dlo   = dv[b];
                const float s     = dlo + dv[b + 1] - 2.0f * delta;
                const int o4 = b * TBL_BIN + par * 128 + tx * 4;
                sm[o4 + 0] = invw;
                sm[o4 + 1] = -cw[b] * invw;
                sm[o4 + 2] = ih;
                sm[o4 + 3] = ch[b];
                const int o2 = b * TBL_BIN + 256 + par * 64 + tx * 2;
                sm[o2 + 0] = dlo;
                sm[o2 + 1] = s;
            }
        }
        __syncthreads();

        // mirror to global and publish
        {
            float4* dst = (float4*)(g_tbl + (size_t)bx * TBL_SZ);
            const float4* src = (const float4*)sm;
            #pragma unroll
            for (int i = 0; i < 7; i++) {
                const int k = tid + i * THREADS;
                if (k < TBL_SZ / 4) dst[k] = src[k];
            }
        }
        __threadfence();
        __syncthreads();
        if (tid == 0) atomicExch(&g_flag[bx], 1);
    } else {
        // ---------------- consumer path ----------------
        if (tid == 0) {
            while (atomicAdd(&g_flag[bx], 0) == 0) __nanosleep(64);
        }
        __syncthreads();
        const float4* src = (const float4*)(g_tbl + (size_t)bx * TBL_SZ);
        float4* dst = (float4*)sm;
        #pragma unroll
        for (int i = 0; i < 7; i++) {
            const int k = tid + i * THREADS;
            if (k < TBL_SZ / 4) dst[k] = __ldcg(src + k);   // L1-bypass: L2-fresh
        }
        __syncthreads();
    }

    // ---------------- persistent tile loop ----------------
    const int tx  = tid & 31;                    // col-pair index
    const int ty  = tid >> 5;                    // row slot 0..3
    const int col = bx * TILE_D + 2 * tx;

    const float* kn = sm + TBL_KN;
    const float ka0 = kn[0*64 + 2*tx],   ka1 = kn[1*64 + 2*tx],   ka2 = kn[2*64 + 2*tx];
    const float ka3 = kn[3*64 + 2*tx],   ka4 = kn[4*64 + 2*tx],   ka5 = kn[5*64 + 2*tx];
    const float ka6 = kn[6*64 + 2*tx];
    const float kb0 = kn[0*64 + 2*tx+1], kb1 = kn[1*64 + 2*tx+1], kb2 = kn[2*64 + 2*tx+1];
    const float kb3 = kn[3*64 + 2*tx+1], kb4 = kn[4*64 + 2*tx+1], kb5 = kn[5*64 + 2*tx+1];
    const float kb6 = kn[6*64 + 2*tx+1];

    const float* qA = sm + 4 * tx;          // float4 record lane base
    const float* qB = sm + 256 + 2 * tx;    // float2 record lane base

    const int RSTRIDE = 4 * NDIMS / 2;               // float2 units per 4-row step
    const int TSTRIDE = GRID_Y * TILE_R * NDIMS / 2; // float2 units per tile stride

    const size_t base0 = (size_t)(blockIdx.y * TILE_R + ty) * NDIMS + col;
    const float2* __restrict__ pin = (const float2*)(inputs + base0);
    float2* __restrict__ po = (float2*)(out_base + base0);
    float2* __restrict__ pl = (float2*)(out_base + (size_t)NROWS * NDIMS + base0);

    #pragma unroll 1
    for (int t = blockIdx.y; t < NTILES; t += GRID_Y) {
        float2 gv[4];
        #pragma unroll
        for (int j = 0; j < 4; j++) gv[j] = pin[j * RSTRIDE];

        #pragma unroll
        for (int j = 0; j < 4; j++) {
            float2 ro, rl;
            rqs_one(gv[j].x, ka0, ka1, ka2, ka3, ka4, ka5, ka6, qA, qB, 0, ro.x, rl.x);
            rqs_one(gv[j].y, kb0, kb1, kb2, kb3, kb4, kb5, kb6, qA, qB, 1, ro.y, rl.y);
            po[j * RSTRIDE] = ro;
            pl[j * RSTRIDE] = rl;
        }
        pin += TSTRIDE;
        po  += TSTRIDE;
        pl  += TSTRIDE;
    }
}

extern "C" void kernel_launch(void* const* d_in, const int* in_sizes, int n_in,
                              void* d_out, int out_size)
{
    const float* inputs = (const float*)d_in[0];
    const float* params = (const float*)d_in[1];
    float* out = (float*)d_out;

    dim3 grid(NBLK_D, GRID_Y);   // (32, 41) = 1312 blocks, single wave at 9 CTAs/SM
    rqs_fused<<<grid, THREADS>>>(inputs, params, out);
}